// round 2
// baseline (speedup 1.0000x reference)
#include <cuda_runtime.h>
#include <cuda_bf16.h>
#include <math.h>

// ============================================================================
// Problem: b=8, c=128, h=w=128, heads=8, hd=16, kvlen = 64+16+4+1 = 85
// ============================================================================

#define NB   8
#define NC   128
#define NH   8
#define HD   16
#define KVL  85

// device scratch (allocation-free rule: __device__ globals)
__device__ float d_tab[128 * 64];              // pos-enc table (h==w so one table)
__device__ float d_y1[NB * NC * KVL];          // depthwise conv output [b][c][row]
__device__ float d_k[NB * NH * KVL * HD];
__device__ float d_v[NB * NH * KVL * HD];

// ----------------------------------------------------------------------------
// f32x2 packed math (Blackwell FFMA2: 2x fp32 FMA per issue)
// ----------------------------------------------------------------------------
__device__ __forceinline__ unsigned long long fma2(unsigned long long a,
                                                   unsigned long long b,
                                                   unsigned long long c) {
    unsigned long long d;
    asm("fma.rn.f32x2 %0, %1, %2, %3;" : "=l"(d) : "l"(a), "l"(b), "l"(c));
    return d;
}
__device__ __forceinline__ unsigned long long mul2(unsigned long long a,
                                                   unsigned long long b) {
    unsigned long long d;
    asm("mul.rn.f32x2 %0, %1, %2;" : "=l"(d) : "l"(a), "l"(b));
    return d;
}
__device__ __forceinline__ unsigned long long splat2(float x) {
    unsigned long long d;
    asm("mov.b64 %0, {%1, %1};" : "=l"(d) : "f"(x));
    return d;
}
__device__ __forceinline__ unsigned long long pack2(float lo, float hi) {
    unsigned long long d;
    asm("mov.b64 %0, {%1, %2};" : "=l"(d) : "f"(lo), "f"(hi));
    return d;
}
__device__ __forceinline__ void unpack2(unsigned long long v, float& lo, float& hi) {
    asm("mov.b64 {%0, %1}, %2;" : "=f"(lo), "=f"(hi) : "l"(v));
}

// ----------------------------------------------------------------------------
// K0: positional-encoding table. tab[y*64 + j]:
//   j<32: sin(y*inv[j]), j>=32: cos(y*inv[j-32]),  inv[i] = 10000^(-(2i)/64)
// posenc[c][y][x] = (c < 64) ? tab[y*64+c] : tab[x*64+(c-64)]
// ----------------------------------------------------------------------------
__global__ void k_tables() {
    int idx = blockIdx.x * blockDim.x + threadIdx.x;
    if (idx >= 128 * 64) return;
    int y = idx >> 6, j = idx & 63;
    int i = j & 31;
    float e = (2.0f * (float)i) / 64.0f;
    float inv = powf(10000.0f, -e);
    float arg = (float)y * inv;
    d_tab[idx] = (j < 32) ? sinf(arg) : cosf(arg);
}

// ----------------------------------------------------------------------------
// K1: per-(b,c): pool xp = x + posenc to 8x8 means; derive 4x4 / 2x2 / 1x1
// (nested means), depthwise 3x3 SAME conv on each grid -> y1[b][c][0..84]
// rows: [0,64) s=8 (row-major), [64,80) s=4, [80,84) s=2, [84] s=1
// ----------------------------------------------------------------------------
__global__ void k_pool_dw(const float* __restrict__ x, const float* __restrict__ dw) {
    __shared__ float pm[64];
    __shared__ float g4[16];
    __shared__ float g2[4];
    __shared__ float g1[1];
    int tid = threadIdx.x;
    int b = blockIdx.x >> 7, c = blockIdx.x & 127;

    if (tid < 64) pm[tid] = 0.0f;
    __syncthreads();

    int xx = tid & 127;
    int rh = tid >> 7;           // 0 or 1: which half of the rows
    int bx = xx >> 4;            // x-bin
    const float* xc = x + ((size_t)(b * NC + c) << 14);
    float peC = (c >= 64) ? d_tab[xx * 64 + (c - 64)] : 0.0f;

    for (int yb = 0; yb < 4; ++yb) {
        float s = 0.0f;
        int y0 = rh * 64 + yb * 16;
#pragma unroll 4
        for (int r = 0; r < 16; ++r) {
            int y = y0 + r;
            float pe = (c < 64) ? d_tab[y * 64 + c] : peC;
            s += xc[(y << 7) + xx] + pe;
        }
        atomicAdd(&pm[(rh * 4 + yb) * 8 + bx], s);
    }
    __syncthreads();
    if (tid < 64) pm[tid] *= (1.0f / 256.0f);
    __syncthreads();

    if (tid < 16) {
        int i = tid >> 2, j = tid & 3;
        g4[tid] = 0.25f * (pm[(2 * i) * 8 + 2 * j] + pm[(2 * i) * 8 + 2 * j + 1] +
                           pm[(2 * i + 1) * 8 + 2 * j] + pm[(2 * i + 1) * 8 + 2 * j + 1]);
    } else if (tid < 20) {
        int t = tid - 16;
        int i = t >> 1, j = t & 1;
        float s = 0.0f;
        for (int yy = 0; yy < 4; ++yy)
            for (int xq = 0; xq < 4; ++xq) s += pm[(4 * i + yy) * 8 + 4 * j + xq];
        g2[t] = s * (1.0f / 16.0f);
    } else if (tid == 20) {
        float s = 0.0f;
        for (int q = 0; q < 64; ++q) s += pm[q];
        g1[0] = s * (1.0f / 64.0f);
    }
    __syncthreads();

    if (tid < KVL) {
        float wv[9];
#pragma unroll
        for (int q = 0; q < 9; ++q) wv[q] = dw[c * 9 + q];
        const float* g;
        int s, ly, lx;
        if (tid < 64)      { g = pm; s = 8; ly = tid >> 3;        lx = tid & 7; }
        else if (tid < 80) { int t = tid - 64; g = g4; s = 4; ly = t >> 2; lx = t & 3; }
        else if (tid < 84) { int t = tid - 80; g = g2; s = 2; ly = t >> 1; lx = t & 1; }
        else               { g = g1; s = 1; ly = 0; lx = 0; }
        float a = 0.0f;
#pragma unroll
        for (int ky = 0; ky < 3; ++ky) {
            int iy = ly + ky - 1;
            bool oky = (iy >= 0) && (iy < s);
#pragma unroll
            for (int kx = 0; kx < 3; ++kx) {
                int ix = lx + kx - 1;
                if (oky && ix >= 0 && ix < s) a += g[iy * s + ix] * wv[ky * 3 + kx];
            }
        }
        d_y1[(b * NC + c) * KVL + tid] = a;
    }
}

// ----------------------------------------------------------------------------
// K2: per-(b,row): pointwise 1x1 -> LayerNorm(c) -> exact GELU -> KV projection
// writes d_k[b][m][row][d], d_v[b][m][row][d]
// ----------------------------------------------------------------------------
__global__ void k_pw_ln_kv(const float* __restrict__ pw, const float* __restrict__ lnw,
                           const float* __restrict__ lnb, const float* __restrict__ Wkv) {
    __shared__ float ycol[128];
    __shared__ float zs[128];
    __shared__ float red[2];
    int tid = threadIdx.x;
    int b = blockIdx.x / KVL;
    int row = blockIdx.x - b * KVL;

    if (tid < 128) ycol[tid] = d_y1[(b * NC + tid) * KVL + row];
    __syncthreads();

    if (tid < 128) {
        float a = 0.0f;
        const float* w = pw + tid * 128;
#pragma unroll 8
        for (int ci = 0; ci < 128; ++ci) a += w[ci] * ycol[ci];
        zs[tid] = a;
    }
    __syncthreads();

    if (tid < 32) {
        float s = zs[tid] + zs[tid + 32] + zs[tid + 64] + zs[tid + 96];
#pragma unroll
        for (int o = 16; o; o >>= 1) s += __shfl_xor_sync(0xffffffffu, s, o);
        if (tid == 0) red[0] = s * (1.0f / 128.0f);
    }
    __syncthreads();
    float mu = red[0];
    if (tid < 32) {
        float s = 0.0f;
#pragma unroll
        for (int q = 0; q < 4; ++q) { float dd = zs[tid + 32 * q] - mu; s += dd * dd; }
#pragma unroll
        for (int o = 16; o; o >>= 1) s += __shfl_xor_sync(0xffffffffu, s, o);
        if (tid == 0) red[1] = s * (1.0f / 128.0f);
    }
    __syncthreads();
    float rstd = rsqrtf(red[1] + 1e-5f);
    if (tid < 128) {
        float zn = (zs[tid] - mu) * rstd * lnw[tid] + lnb[tid];
        zs[tid] = 0.5f * zn * (1.0f + erff(zn * 0.70710678118654752f));
    }
    __syncthreads();

    // KV projection: Wkv rows 0..127 -> k, 128..255 -> v; row = m*16+d
    float a = 0.0f;
    const float* w = Wkv + tid * 128;
#pragma unroll 8
    for (int ci = 0; ci < 128; ++ci) a += w[ci] * zs[ci];
    int m = (tid >> 4) & 7, d = tid & 15;
    float* dst = (tid < 128) ? d_k : d_v;
    dst[((size_t)(b * NH + m) * KVL + row) * HD + d] = a;
}

// ----------------------------------------------------------------------------
// K3: fused main kernel: one block per (b, image row y) = 128 query pixels
//   Q = Xp(128x128ch) @ Wq^T  ->  softmax attention over 85 KV  ->
//   Out = O @ Wproj^T + bias  -> global (channel-major), coalesced
// ----------------------------------------------------------------------------
#define STR   132                      // padded smem row stride (floats)
#define KVS   (KVL * HD)               // 1360
#define OFF_B (128 * STR)              // 16896
#define OFF_K (2 * 128 * STR)          // 33792
#define OFF_V (OFF_K + NH * KVS)       // 44672
#define SMEMF (OFF_V + NH * KVS)       // 55552 floats = 222208 bytes

// 128x128x128 GEMM: out[x][o] = sum_c A[c*STR+x] * B[c*STR+o]
// thread (tx=tid&15, ty=tid>>4): x in {tx*4+i, 64+tx*4+i}, o in {ty*8+j}
__device__ __forceinline__ void gemm128(const float* __restrict__ A,
                                        const float* __restrict__ B,
                                        int tx, int ty,
                                        unsigned long long acc[8][4]) {
#pragma unroll
    for (int j = 0; j < 8; ++j)
#pragma unroll
        for (int i = 0; i < 4; ++i) acc[j][i] = 0ull;
    const float* ap = A + tx * 4;
    const float* bp = B + ty * 8;
#pragma unroll 4
    for (int k = 0; k < 128; ++k) {
        ulonglong2 a01 = *(const ulonglong2*)(ap);
        ulonglong2 a23 = *(const ulonglong2*)(ap + 64);
        float4 b0 = *(const float4*)(bp);
        float4 b1 = *(const float4*)(bp + 4);
        ap += STR; bp += STR;
        float bf[8] = {b0.x, b0.y, b0.z, b0.w, b1.x, b1.y, b1.z, b1.w};
#pragma unroll
        for (int j = 0; j < 8; ++j) {
            unsigned long long bb = splat2(bf[j]);
            acc[j][0] = fma2(a01.x, bb, acc[j][0]);
            acc[j][1] = fma2(a01.y, bb, acc[j][1]);
            acc[j][2] = fma2(a23.x, bb, acc[j][2]);
            acc[j][3] = fma2(a23.y, bb, acc[j][3]);
        }
    }
}

__global__ void __launch_bounds__(256, 1)
k_main(const float* __restrict__ x, const float* __restrict__ Wq,
       const float* __restrict__ Wproj, const float* __restrict__ bproj,
       float* __restrict__ out) {
    extern __shared__ float sm[];
    float* As = sm;                // region 1: Xp then O (channel-major [c][x])
    float* Bs = sm + OFF_B;        // region 2: Wq^T -> Q^T -> Wproj^T
    float* Ks = sm + OFF_K;
    float* Vs = sm + OFF_V;
    int tid = threadIdx.x;
    int b = blockIdx.x >> 7;
    int y = blockIdx.x & 127;

    // load K/V for this batch (contiguous copy; KVS == KVL*HD)
    {
        const float* kg = d_k + (size_t)b * NH * KVS;
        const float* vg = d_v + (size_t)b * NH * KVS;
        for (int i = tid; i < NH * KVS; i += 256) {
            Ks[i] = kg[i];
            Vs[i] = vg[i];
        }
    }
    // load Xp row (with pos-enc) channel-major: As[c*STR + xx]
    for (int i = tid; i < 16384; i += 256) {
        int c = i >> 7, xx = i & 127;
        float pe = (c < 64) ? d_tab[y * 64 + c] : d_tab[xx * 64 + (c - 64)];
        As[c * STR + xx] = x[((size_t)(b * NC + c) << 14) + (y << 7) + xx] + pe;
    }
    // Bs[c*STR + o] = Wq[o][c]
    for (int i = tid; i < 16384; i += 256) {
        int o = i >> 7, c = i & 127;
        Bs[c * STR + o] = Wq[i];
    }
    __syncthreads();

    int tx = tid & 15, ty = tid >> 4;
    unsigned long long acc[8][4];

    // ---- Q-GEMM ----
    gemm128(As, Bs, tx, ty, acc);
    __syncthreads();  // all Wq reads done; Bs becomes Q^T

    // write Q transposed: Qs[o*STR + x]
#pragma unroll
    for (int j = 0; j < 8; ++j) {
        float* q = Bs + (ty * 8 + j) * STR;
        float l0, h0, l1, h1;
        unpack2(acc[j][0], l0, h0); unpack2(acc[j][1], l1, h1);
        *(float4*)(q + tx * 4) = make_float4(l0, h0, l1, h1);
        unpack2(acc[j][2], l0, h0); unpack2(acc[j][3], l1, h1);
        *(float4*)(q + 64 + tx * 4) = make_float4(l0, h0, l1, h1);
    }
    __syncthreads();

    // ---- attention: 1024 (x, head) pairs, 4 per thread ----
    const float* Qs = Bs;
    float* Os = As;  // As (Xp) is dead; reuse as O (channel-major)
#pragma unroll 1
    for (int p = 0; p < 4; ++p) {
        int pair = p * 256 + tid;
        int m = pair >> 7;          // warp-uniform (K/V loads broadcast)
        int xx = pair & 127;

        unsigned long long q2[8];
#pragma unroll
        for (int i = 0; i < 8; ++i)
            q2[i] = pack2(Qs[(m * 16 + 2 * i) * STR + xx],
                          Qs[(m * 16 + 2 * i + 1) * STR + xx]);

        const unsigned long long* kb = (const unsigned long long*)(Ks + m * KVS);
        const unsigned long long* vb = (const unsigned long long*)(Vs + m * KVS);

        float lg[KVL];
#pragma unroll
        for (int j = 0; j < KVL; ++j) {
            const unsigned long long* kj = kb + j * 8;
            unsigned long long a0 = mul2(q2[0], kj[0]);
            unsigned long long a1 = mul2(q2[1], kj[1]);
#pragma unroll
            for (int i = 2; i < 8; i += 2) {
                a0 = fma2(q2[i], kj[i], a0);
                a1 = fma2(q2[i + 1], kj[i + 1], a1);
            }
            float l0, h0, l1, h1;
            unpack2(a0, l0, h0); unpack2(a1, l1, h1);
            lg[j] = (l0 + h0) + (l1 + h1);
        }
        float mx = lg[0];
#pragma unroll
        for (int j = 1; j < KVL; ++j) mx = fmaxf(mx, lg[j]);
        mx *= 0.25f;                               // hd^-0.5 = 0.25 scale
        float ssum = 0.0f;
#pragma unroll
        for (int j = 0; j < KVL; ++j) {
            float e = __expf(lg[j] * 0.25f - mx);
            lg[j] = e;
            ssum += e;
        }
        float inv = 1.0f / ssum;

        unsigned long long oa[8];
#pragma unroll
        for (int i = 0; i < 8; ++i) oa[i] = 0ull;
#pragma unroll
        for (int j = 0; j < KVL; ++j) {
            unsigned long long pj = splat2(lg[j]);
            const unsigned long long* vj = vb + j * 8;
#pragma unroll
            for (int i = 0; i < 8; ++i) oa[i] = fma2(pj, vj[i], oa[i]);
        }
#pragma unroll
        for (int i = 0; i < 8; ++i) {
            float lo, hi;
            unpack2(oa[i], lo, hi);
            Os[(m * 16 + 2 * i) * STR + xx] = lo * inv;
            Os[(m * 16 + 2 * i + 1) * STR + xx] = hi * inv;
        }
    }
    __syncthreads();

    // ---- out-proj GEMM ----
    for (int i = tid; i < 16384; i += 256) {
        int o = i >> 7, c = i & 127;
        Bs[c * STR + o] = Wproj[i];
    }
    __syncthreads();
    gemm128(Os, Bs, tx, ty, acc);

    float* og = out + (size_t)b * NC * 16384 + (y << 7);
#pragma unroll
    for (int j = 0; j < 8; ++j) {
        int oc = ty * 8 + j;
        float bv = bproj[oc];
        float* orow = og + (size_t)oc * 16384;
        float l0, h0, l1, h1;
        unpack2(acc[j][0], l0, h0); unpack2(acc[j][1], l1, h1);
        *(float4*)(orow + tx * 4) = make_float4(l0 + bv, h0 + bv, l1 + bv, h1 + bv);
        unpack2(acc[j][2], l0, h0); unpack2(acc[j][3], l1, h1);
        *(float4*)(orow + 64 + tx * 4) = make_float4(l0 + bv, h0 + bv, l1 + bv, h1 + bv);
    }
}

// ----------------------------------------------------------------------------
extern "C" void kernel_launch(void* const* d_in, const int* in_sizes, int n_in,
                              void* d_out, int out_size) {
    const float* x     = (const float*)d_in[0];
    const float* Wq    = (const float*)d_in[1];
    const float* Wkv   = (const float*)d_in[2];
    const float* Wproj = (const float*)d_in[3];
    const float* bproj = (const float*)d_in[4];
    const float* dw    = (const float*)d_in[5];
    const float* pw    = (const float*)d_in[6];
    const float* lnw   = (const float*)d_in[7];
    const float* lnb   = (const float*)d_in[8];
    float* out = (float*)d_out;

    cudaFuncSetAttribute(k_main, cudaFuncAttributeMaxDynamicSharedMemorySize,
                         SMEMF * (int)sizeof(float));

    k_tables<<<32, 256>>>();
    k_pool_dw<<<NB * NC, 256>>>(x, dw);
    k_pw_ln_kv<<<NB * KVL, 256>>>(pw, lnw, lnb, Wkv);
    k_main<<<NB * 128, 256, SMEMF * sizeof(float)>>>(x, Wq, Wproj, bproj, out);
}